// round 11
// baseline (speedup 1.0000x reference)
#include <cuda_runtime.h>
#include <cuda_fp16.h>
#include <cstdint>

// Problem constants
#define B_  32
#define T_  4096
#define M_  256     // K dim of GEMM
#define L_  128     // hidden (N dim of GEMM)

#define PAIRS     64            // (b,t) pairs per CTA
#define ROWS      128           // MMA rows: h1 rows 0..63, h2 rows 64..127
#define NTHREADS  256           // 8 warps: (4 row-groups x 2 col-halves)
#define KCHUNK    16            // fp32 elems per k-chunk (1 kstep)
#define NCHUNKS   16

#define HSTRIDE   24            // fp16 elems per H tile row (48B; 12-bank rotation, conflict-free)
#define VSTRIDE   264           // fp16 elems per V row (528B; proven)

#define RING_SLOT 8192          // one chunk: 128 rows x 16 fp32
#define HBUF_B    (ROWS * HSTRIDE * 2)       // 6144 B per fp16 H buffer

// smem byte offsets
#define SM_RING   0                          // 4 x 8192 = 32768
#define SM_H      32768                      // 2 x 6144 = 12288
#define SM_V      45056                      // 128 x 264 fp16 = 67584
#define SM_WS     112640                     // 128 floats
#define SM_SCORE  113152                     // 2 x 128 floats
#define SMEM_BYTES 114176

__device__ __half g_Vh[L_ * M_];

__device__ __forceinline__ float fast_tanh(float x) {
    float e = __expf(2.0f * x);
    return 1.0f - __fdividef(2.0f, e + 1.0f);
}

__device__ __forceinline__ uint32_t pack2h(float a, float b) {
    __half2 hv; hv.x = __float2half_rn(a); hv.y = __float2half_rn(b);
    return *reinterpret_cast<uint32_t*>(&hv);
}

__device__ __forceinline__ void mma_f16(float* c, const uint32_t* a,
                                        uint32_t b0, uint32_t b1) {
    asm("mma.sync.aligned.m16n8k16.row.col.f32.f16.f16.f32 "
        "{%0,%1,%2,%3}, {%4,%5,%6,%7}, {%8,%9}, {%0,%1,%2,%3};\n"
        : "+f"(c[0]), "+f"(c[1]), "+f"(c[2]), "+f"(c[3])
        : "r"(a[0]), "r"(a[1]), "r"(a[2]), "r"(a[3]), "r"(b0), "r"(b1));
}

__device__ __forceinline__ void ldsm4(uint32_t& r0, uint32_t& r1, uint32_t& r2, uint32_t& r3,
                                      uint32_t addr) {
    asm volatile("ldmatrix.sync.aligned.m8n8.x4.shared.b16 {%0,%1,%2,%3}, [%4];\n"
                 : "=r"(r0), "=r"(r1), "=r"(r2), "=r"(r3) : "r"(addr));
}

__device__ __forceinline__ void cp16(uint32_t dst, const void* src) {
    asm volatile("cp.async.cg.shared.global [%0], [%1], 16;\n"
                 :: "r"(dst), "l"(src) : "memory");
}
#define CP_COMMIT() asm volatile("cp.async.commit_group;\n" ::: "memory")
#define CP_WAIT(n)  asm volatile("cp.async.wait_group %0;\n" :: "n"(n) : "memory")

// ---------------- kernel 1: round V to fp16 ----------------
__global__ void vprep_kernel(const float* __restrict__ v_tp) {
    int i = blockIdx.x * blockDim.x + threadIdx.x;
    if (i < L_ * M_) g_Vh[i] = __float2half_rn(v_tp[i]);
}

// ---------------- kernel 2: main ----------------
extern __shared__ char smem[];

__global__ void __launch_bounds__(NTHREADS, 2)
topo_attn_kernel(const float* __restrict__ h1, const float* __restrict__ h2,
                 const float* __restrict__ w_tp, float* __restrict__ out)
{
    uint32_t sb;
    asm("{ .reg .u64 t; cvta.to.shared.u64 t, %1; cvt.u32.u64 %0, t; }"
        : "=r"(sb) : "l"(smem));

    const int tid  = threadIdx.x;
    const int warp = tid >> 5;
    const int lane = tid & 31;
    const int pair0 = blockIdx.x * PAIRS;

    float* ws     = reinterpret_cast<float*>(smem + SM_WS);
    float* scoreA = reinterpret_cast<float*>(smem + SM_SCORE);          // col half 0
    float* scoreB = scoreA + 128;                                       // col half 1
    __half* Vs    = reinterpret_cast<__half*>(smem + SM_V);

    // per-thread H staging: row r, 2 consecutive 16B columns
    const int hrow = tid >> 1;                 // 0..127
    const int hc   = (tid & 1) * 2;            // c4 base: 0 or 2
    const float* hptr = (hrow < PAIRS)
        ? (h1 + (size_t)(pair0 + hrow) * M_)
        : (h2 + (size_t)(pair0 + hrow - PAIRS) * M_);

    const uint32_t ring0 = sb + SM_RING + tid * 16;   // j=0 slot base (within slot add j*4096)

    // ---- prologue: issue cp.async for chunks 0..2
    #pragma unroll
    for (int p = 0; p < 3; ++p) {
        cp16(ring0 + p * RING_SLOT,        hptr + p * KCHUNK + hc * 4);
        cp16(ring0 + p * RING_SLOT + 4096, hptr + p * KCHUNK + (hc + 1) * 4);
        CP_COMMIT();
    }

    // ---- while they fly: copy V (fp16, L2-resident) and w into smem
    if (tid < L_) ws[tid] = w_tp[tid];
    #pragma unroll
    for (int i = 0; i < 16; ++i) {
        int idx = i * NTHREADS + tid;      // uint4 idx over 128*32
        int r   = idx >> 5;
        int c8  = idx & 31;
        uint4 v = *reinterpret_cast<const uint4*>(g_Vh + r * M_ + c8 * 8);
        *reinterpret_cast<uint4*>(Vs + r * VSTRIDE + c8 * 8) = v;
    }
    __syncthreads();   // V + ws visible

    // warp tiling: 4 row-groups x 2 col-halves
    const int wr = warp >> 1;
    const int wc = warp & 1;
    const int rb = wr * 32;
    const int cb = wc * 64;

    // ldmatrix lane-address decomposition
    const int arow = (lane & 7) + ((lane >> 3) & 1) * 8;
    const int acol = (lane >> 4) * 8;
    const int brow = (lane & 7) + ((lane >> 4) & 1) * 8;
    const int bcol = ((lane >> 3) & 1) * 8;

    const uint32_t a_h0 = sb + SM_H + ((rb + arow) * HSTRIDE + acol) * 2;
    const uint32_t b_v0 = sb + SM_V + ((cb + brow) * VSTRIDE + bcol) * 2;

    float acc[2][8][4];
    #pragma unroll
    for (int rt = 0; rt < 2; ++rt)
        #pragma unroll
        for (int n = 0; n < 8; ++n)
            #pragma unroll
            for (int q = 0; q < 4; ++q) acc[rt][n][q] = 0.0f;

    for (int kc = 0; kc < NCHUNKS; ++kc) {
        // ---- issue chunk kc+3 (clamped at tail -> dead slot, keeps wait imm constant)
        {
            int src_k = (kc + 3 < NCHUNKS) ? (kc + 3) : (NCHUNKS - 1);
            int slot  = (kc + 3) & 3;
            cp16(ring0 + slot * RING_SLOT,        hptr + src_k * KCHUNK + hc * 4);
            cp16(ring0 + slot * RING_SLOT + 4096, hptr + src_k * KCHUNK + (hc + 1) * 4);
            CP_COMMIT();
        }
        CP_WAIT(3);    // this thread's chunk-kc staging complete

        // ---- read own staged fp32, cvt, store fp16 tile
        {
            const int slot = kc & 3;
            float4 f0 = *reinterpret_cast<const float4*>(smem + SM_RING + slot * RING_SLOT + tid * 16);
            float4 f1 = *reinterpret_cast<const float4*>(smem + SM_RING + slot * RING_SLOT + 4096 + tid * 16);
            __half* Hs = reinterpret_cast<__half*>(smem + SM_H + (kc & 1) * HBUF_B);
            uint2 v0, v1;
            v0.x = pack2h(f0.x, f0.y); v0.y = pack2h(f0.z, f0.w);
            v1.x = pack2h(f1.x, f1.y); v1.y = pack2h(f1.z, f1.w);
            *reinterpret_cast<uint2*>(Hs + hrow * HSTRIDE + hc * 4)       = v0;
            *reinterpret_cast<uint2*>(Hs + hrow * HSTRIDE + (hc + 1) * 4) = v1;
        }
        __syncthreads();   // hbuf[kc&1] ready; separates mma(kc-2) from this overwrite

        // ---- mma: one k16 step
        {
            const uint32_t a_hb = a_h0 + (kc & 1) * HBUF_B;
            uint32_t a0[4], a1[4];
            ldsm4(a0[0], a0[1], a0[2], a0[3], a_hb);
            ldsm4(a1[0], a1[1], a1[2], a1[3], a_hb + 16 * HSTRIDE * 2);
            const uint32_t kb = kc * KCHUNK * 2;
            #pragma unroll
            for (int p = 0; p < 4; ++p) {
                uint32_t b0, b1, b2, b3;
                ldsm4(b0, b1, b2, b3, b_v0 + p * (16 * VSTRIDE * 2) + kb);
                mma_f16(acc[0][2 * p],     a0, b0, b1);
                mma_f16(acc[0][2 * p + 1], a0, b2, b3);
                mma_f16(acc[1][2 * p],     a1, b0, b1);
                mma_f16(acc[1][2 * p + 1], a1, b2, b3);
            }
        }
    }

    // ---- epilogue: partial score over this warp's 64 columns
    {
        const int g = lane >> 2;
        const int t = lane & 3;
        float p0[2], p1[2];
        #pragma unroll
        for (int rt = 0; rt < 2; ++rt) { p0[rt] = 0.f; p1[rt] = 0.f; }
        #pragma unroll
        for (int nt = 0; nt < 8; ++nt) {
            float w0 = ws[cb + nt * 8 + 2 * t];
            float w1 = ws[cb + nt * 8 + 2 * t + 1];
            #pragma unroll
            for (int rt = 0; rt < 2; ++rt) {
                p0[rt] += w0 * fast_tanh(acc[rt][nt][0]) + w1 * fast_tanh(acc[rt][nt][1]);
                p1[rt] += w0 * fast_tanh(acc[rt][nt][2]) + w1 * fast_tanh(acc[rt][nt][3]);
            }
        }
        #pragma unroll
        for (int off = 1; off < 4; off <<= 1) {
            #pragma unroll
            for (int rt = 0; rt < 2; ++rt) {
                p0[rt] += __shfl_xor_sync(0xffffffffu, p0[rt], off);
                p1[rt] += __shfl_xor_sync(0xffffffffu, p1[rt], off);
            }
        }
        if (t == 0) {
            float* sc = wc ? scoreB : scoreA;
            #pragma unroll
            for (int rt = 0; rt < 2; ++rt) {
                sc[rb + rt * 16 + g]     = p0[rt];
                sc[rb + rt * 16 + g + 8] = p1[rt];
            }
        }
    }
    __syncthreads();

    // ---- 2-way softmax + store. out shape (B, 2, T)
    if (tid < PAIRS) {
        float s1 = scoreA[tid]         + scoreB[tid];
        float s2 = scoreA[PAIRS + tid] + scoreB[PAIRS + tid];
        float d  = s2 - s1;
        float a1 = 1.0f / (1.0f + __expf(d));
        float a2 = 1.0f / (1.0f + __expf(-d));
        int gp = pair0 + tid;
        int b  = gp >> 12;          // / T_
        int tt = gp & (T_ - 1);
        out[(size_t)b * (2 * T_) + tt]      = a1;
        out[(size_t)b * (2 * T_) + T_ + tt] = a2;
    }
}

extern "C" void kernel_launch(void* const* d_in, const int* in_sizes, int n_in,
                              void* d_out, int out_size) {
    const float* h1   = (const float*)d_in[0];
    const float* h2   = (const float*)d_in[1];
    const float* w_tp = (const float*)d_in[2];
    const float* v_tp = (const float*)d_in[3];
    float* out = (float*)d_out;

    cudaFuncSetAttribute(topo_attn_kernel,
                         cudaFuncAttributeMaxDynamicSharedMemorySize, SMEM_BYTES);

    vprep_kernel<<<(L_ * M_ + 255) / 256, 256>>>(v_tp);

    int grid = (B_ * T_) / PAIRS;   // 2048
    topo_attn_kernel<<<grid, NTHREADS, SMEM_BYTES>>>(h1, h2, w_tp, out);
}

// round 12
// speedup vs baseline: 1.3360x; 1.3360x over previous
#include <cuda_runtime.h>
#include <cuda_fp16.h>
#include <cstdint>

// Problem constants
#define B_  32
#define T_  4096
#define M_  256     // K dim of GEMM
#define L_  128     // hidden (N dim of GEMM)

#define PAIRS     64            // (b,t) pairs per CTA
#define ROWS      128           // MMA rows: h1 rows 0..63, h2 rows 64..127
#define NTHREADS  256           // 8 warps: (4 row-groups x 2 col-halves)
#define KCHUNK    32            // fp32 elems per k-chunk
#define NCHUNKS   8

#define HSTRIDE   40            // fp16 elems per H tile row (80B; proven conflict-free)
#define VSTRIDE   264           // fp16 elems per V row (528B; proven)

#define HBUF_B    (ROWS * HSTRIDE * 2)       // 10240 B per H buffer

// smem byte offsets
#define SM_H      0                          // 2 x 10240 B (double buffer)
#define SM_V      20480                      // 128 x 264 fp16 = 67584 B
#define SM_WS     88064                      // 128 floats
#define SM_SCORE  88576                      // 2 x 128 floats (per column-half)
#define SMEM_BYTES 89600

__device__ __half g_Vh[L_ * M_];

__device__ __forceinline__ float fast_tanh(float x) {
    float e = __expf(2.0f * x);
    return 1.0f - __fdividef(2.0f, e + 1.0f);
}

__device__ __forceinline__ uint32_t pack2h(float a, float b) {
    __half2 hv; hv.x = __float2half_rn(a); hv.y = __float2half_rn(b);
    return *reinterpret_cast<uint32_t*>(&hv);
}

__device__ __forceinline__ void mma_f16(float* c, const uint32_t* a,
                                        uint32_t b0, uint32_t b1) {
    asm("mma.sync.aligned.m16n8k16.row.col.f32.f16.f16.f32 "
        "{%0,%1,%2,%3}, {%4,%5,%6,%7}, {%8,%9}, {%0,%1,%2,%3};\n"
        : "+f"(c[0]), "+f"(c[1]), "+f"(c[2]), "+f"(c[3])
        : "r"(a[0]), "r"(a[1]), "r"(a[2]), "r"(a[3]), "r"(b0), "r"(b1));
}

__device__ __forceinline__ void ldsm4(uint32_t& r0, uint32_t& r1, uint32_t& r2, uint32_t& r3,
                                      uint32_t addr) {
    asm volatile("ldmatrix.sync.aligned.m8n8.x4.shared.b16 {%0,%1,%2,%3}, [%4];\n"
                 : "=r"(r0), "=r"(r1), "=r"(r2), "=r"(r3) : "r"(addr));
}

// ---------------- kernel 1: round V to fp16 ----------------
__global__ void vprep_kernel(const float* __restrict__ v_tp) {
    int i = blockIdx.x * blockDim.x + threadIdx.x;
    if (i < L_ * M_) g_Vh[i] = __float2half_rn(v_tp[i]);
}

// ---------------- kernel 2: main ----------------
extern __shared__ char smem[];

__global__ void __launch_bounds__(NTHREADS, 2)
topo_attn_kernel(const float* __restrict__ h1, const float* __restrict__ h2,
                 const float* __restrict__ w_tp, float* __restrict__ out)
{
    uint32_t sb;
    asm("{ .reg .u64 t; cvta.to.shared.u64 t, %1; cvt.u32.u64 %0, t; }"
        : "=r"(sb) : "l"(smem));

    const int tid  = threadIdx.x;
    const int warp = tid >> 5;
    const int lane = tid & 31;
    const int pair0 = blockIdx.x * PAIRS;

    float* ws     = reinterpret_cast<float*>(smem + SM_WS);
    float* scoreA = reinterpret_cast<float*>(smem + SM_SCORE);          // col half 0
    float* scoreB = scoreA + 128;                                       // col half 1
    __half* Vs    = reinterpret_cast<__half*>(smem + SM_V);

    // per-thread H staging coords: 4 float4 per chunk over (128 rows x 8 c4)
    const int hr  = tid >> 3;          // 0..31 (+32*i)
    const int hc4 = tid & 7;

    const float* hsrc[4];
    #pragma unroll
    for (int i = 0; i < 4; ++i) {
        int rr = hr + i * 32;
        hsrc[i] = (rr < PAIRS)
            ? (h1 + (size_t)(pair0 + rr) * M_)
            : (h2 + (size_t)(pair0 + rr - PAIRS) * M_);
    }

    // ---- issue chunk-0 LDGs immediately
    float4 f[4];
    #pragma unroll
    for (int i = 0; i < 4; ++i)
        f[i] = *reinterpret_cast<const float4*>(hsrc[i] + hc4 * 4);

    // ---- while they fly: copy V (fp16, L2-resident) and w into smem
    if (tid < L_) ws[tid] = w_tp[tid];
    #pragma unroll
    for (int i = 0; i < 16; ++i) {
        int idx = i * NTHREADS + tid;      // uint4 idx over 128*32
        int r   = idx >> 5;
        int c8  = idx & 31;
        uint4 v = *reinterpret_cast<const uint4*>(g_Vh + r * M_ + c8 * 8);
        *reinterpret_cast<uint4*>(Vs + r * VSTRIDE + c8 * 8) = v;
    }

    // ---- cvt+STS chunk 0 into buf0, then prefetch chunk 1
    {
        __half* Hs = reinterpret_cast<__half*>(smem + SM_H);
        #pragma unroll
        for (int i = 0; i < 4; ++i) {
            uint2 hv;
            hv.x = pack2h(f[i].x, f[i].y);
            hv.y = pack2h(f[i].z, f[i].w);
            *reinterpret_cast<uint2*>(Hs + (hr + i * 32) * HSTRIDE + hc4 * 4) = hv;
        }
        #pragma unroll
        for (int i = 0; i < 4; ++i)
            f[i] = *reinterpret_cast<const float4*>(hsrc[i] + KCHUNK + hc4 * 4);
    }
    __syncthreads();   // V + ws + buf0 visible

    // warp tiling: 4 row-groups x 2 col-halves
    const int wr = warp >> 1;
    const int wc = warp & 1;
    const int rb = wr * 32;
    const int cb = wc * 64;

    // ldmatrix lane-address decomposition (within a 16-row / 16-col tile)
    const int arow = (lane & 7) + ((lane >> 3) & 1) * 8;
    const int acol = (lane >> 4) * 8;
    const int brow = (lane & 7) + ((lane >> 4) & 1) * 8;
    const int bcol = ((lane >> 3) & 1) * 8;

    const uint32_t a_h0 = sb + SM_H + ((rb + arow) * HSTRIDE + acol) * 2;
    const uint32_t b_v0 = sb + SM_V + ((cb + brow) * VSTRIDE + bcol) * 2;

    float acc[2][8][4];                // [row-tile m16][col-tile n8][frag]
    #pragma unroll
    for (int rt = 0; rt < 2; ++rt)
        #pragma unroll
        for (int n = 0; n < 8; ++n)
            #pragma unroll
            for (int q = 0; q < 4; ++q) acc[rt][n][q] = 0.0f;

    for (int kc = 0; kc < NCHUNKS; ++kc) {
        const int buf = kc & 1;
        const uint32_t a_hb = a_h0 + buf * HBUF_B;
        const uint32_t kb   = kc * KCHUNK * 2;

        // ---- kstep 0: issue fragment loads first (latency hides under cvt below)
        uint32_t a0[4], a1[4];
        ldsm4(a0[0], a0[1], a0[2], a0[3], a_hb);
        ldsm4(a1[0], a1[1], a1[2], a1[3], a_hb + 16 * HSTRIDE * 2);
        uint32_t b0[4], b1[4], b2[4], b3[4];
        ldsm4(b0[0], b0[1], b0[2], b0[3], b_v0 + 0 * (16 * VSTRIDE * 2) + kb);
        ldsm4(b1[0], b1[1], b1[2], b1[3], b_v0 + 1 * (16 * VSTRIDE * 2) + kb);
        ldsm4(b2[0], b2[1], b2[2], b2[3], b_v0 + 2 * (16 * VSTRIDE * 2) + kb);
        ldsm4(b3[0], b3[1], b3[2], b3[3], b_v0 + 3 * (16 * VSTRIDE * 2) + kb);

        // ---- cvt + STS chunk kc+1 into the other buffer (fills LDSM shadow;
        //      readers of that buffer finished at sync of iter kc-1)
        if (kc + 1 < NCHUNKS) {
            __half* Hn = reinterpret_cast<__half*>(smem + SM_H + (buf ^ 1) * HBUF_B);
            #pragma unroll
            for (int i = 0; i < 4; ++i) {
                uint2 hv;
                hv.x = pack2h(f[i].x, f[i].y);
                hv.y = pack2h(f[i].z, f[i].w);
                *reinterpret_cast<uint2*>(Hn + (hr + i * 32) * HSTRIDE + hc4 * 4) = hv;
            }
        }

        // ---- kstep 0 mma
        mma_f16(acc[0][0], a0, b0[0], b0[1]);
        mma_f16(acc[0][1], a0, b0[2], b0[3]);
        mma_f16(acc[1][0], a1, b0[0], b0[1]);
        mma_f16(acc[1][1], a1, b0[2], b0[3]);
        mma_f16(acc[0][2], a0, b1[0], b1[1]);
        mma_f16(acc[0][3], a0, b1[2], b1[3]);
        mma_f16(acc[1][2], a1, b1[0], b1[1]);
        mma_f16(acc[1][3], a1, b1[2], b1[3]);
        mma_f16(acc[0][4], a0, b2[0], b2[1]);
        mma_f16(acc[0][5], a0, b2[2], b2[3]);
        mma_f16(acc[1][4], a1, b2[0], b2[1]);
        mma_f16(acc[1][5], a1, b2[2], b2[3]);
        mma_f16(acc[0][6], a0, b3[0], b3[1]);
        mma_f16(acc[0][7], a0, b3[2], b3[3]);
        mma_f16(acc[1][6], a1, b3[0], b3[1]);
        mma_f16(acc[1][7], a1, b3[2], b3[3]);

        // ---- kstep 1
        {
            const uint32_t kk2 = 16 * 2;
            ldsm4(a0[0], a0[1], a0[2], a0[3], a_hb + kk2);
            ldsm4(a1[0], a1[1], a1[2], a1[3], a_hb + kk2 + 16 * HSTRIDE * 2);
            #pragma unroll
            for (int p = 0; p < 4; ++p) {
                uint32_t c0, c1, c2, c3;
                ldsm4(c0, c1, c2, c3, b_v0 + p * (16 * VSTRIDE * 2) + kb + kk2);
                mma_f16(acc[0][2 * p],     a0, c0, c1);
                mma_f16(acc[0][2 * p + 1], a0, c2, c3);
                mma_f16(acc[1][2 * p],     a1, c0, c1);
                mma_f16(acc[1][2 * p + 1], a1, c2, c3);
            }
        }

        // ---- issue LDG for chunk kc+2 (consumed by cvt in iter kc+1)
        if (kc + 2 < NCHUNKS) {
            #pragma unroll
            for (int i = 0; i < 4; ++i)
                f[i] = *reinterpret_cast<const float4*>(hsrc[i] + (kc + 2) * KCHUNK + hc4 * 4);
        }

        if (kc + 1 < NCHUNKS) __syncthreads();   // buf^1 staged by all; all done reading buf
    }

    // ---- epilogue: partial score over this warp's 64 columns
    {
        const int g = lane >> 2;
        const int t = lane & 3;
        float p0[2], p1[2];             // [row-tile] rows g / g+8
        #pragma unroll
        for (int rt = 0; rt < 2; ++rt) { p0[rt] = 0.f; p1[rt] = 0.f; }
        #pragma unroll
        for (int nt = 0; nt < 8; ++nt) {
            float w0 = ws[cb + nt * 8 + 2 * t];
            float w1 = ws[cb + nt * 8 + 2 * t + 1];
            #pragma unroll
            for (int rt = 0; rt < 2; ++rt) {
                p0[rt] += w0 * fast_tanh(acc[rt][nt][0]) + w1 * fast_tanh(acc[rt][nt][1]);
                p1[rt] += w0 * fast_tanh(acc[rt][nt][2]) + w1 * fast_tanh(acc[rt][nt][3]);
            }
        }
        #pragma unroll
        for (int off = 1; off < 4; off <<= 1) {
            #pragma unroll
            for (int rt = 0; rt < 2; ++rt) {
                p0[rt] += __shfl_xor_sync(0xffffffffu, p0[rt], off);
                p1[rt] += __shfl_xor_sync(0xffffffffu, p1[rt], off);
            }
        }
        if (t == 0) {
            float* sc = wc ? scoreB : scoreA;
            #pragma unroll
            for (int rt = 0; rt < 2; ++rt) {
                sc[rb + rt * 16 + g]     = p0[rt];
                sc[rb + rt * 16 + g + 8] = p1[rt];
            }
        }
    }
    __syncthreads();

    // ---- 2-way softmax + store. out shape (B, 2, T)
    if (tid < PAIRS) {
        float s1 = scoreA[tid]         + scoreB[tid];
        float s2 = scoreA[PAIRS + tid] + scoreB[PAIRS + tid];
        float d  = s2 - s1;
        float a1 = 1.0f / (1.0f + __expf(d));
        float a2 = 1.0f / (1.0f + __expf(-d));
        int gp = pair0 + tid;
        int b  = gp >> 12;          // / T_
        int tt = gp & (T_ - 1);
        out[(size_t)b * (2 * T_) + tt]      = a1;
        out[(size_t)b * (2 * T_) + T_ + tt] = a2;
    }
}

extern "C" void kernel_launch(void* const* d_in, const int* in_sizes, int n_in,
                              void* d_out, int out_size) {
    const float* h1   = (const float*)d_in[0];
    const float* h2   = (const float*)d_in[1];
    const float* w_tp = (const float*)d_in[2];
    const float* v_tp = (const float*)d_in[3];
    float* out = (float*)d_out;

    cudaFuncSetAttribute(topo_attn_kernel,
                         cudaFuncAttributeMaxDynamicSharedMemorySize, SMEM_BYTES);

    vprep_kernel<<<(L_ * M_ + 255) / 256, 256>>>(v_tp);

    int grid = (B_ * T_) / PAIRS;   // 2048
    topo_attn_kernel<<<grid, NTHREADS, SMEM_BYTES>>>(h1, h2, w_tp, out);
}

// round 14
// speedup vs baseline: 1.3858x; 1.0373x over previous
#include <cuda_runtime.h>
#include <cuda_fp16.h>
#include <cstdint>

// Problem constants
#define B_  32
#define T_  4096
#define M_  256     // K dim of GEMM
#define L_  128     // hidden (N dim of GEMM)

#define PAIRS     64            // (b,t) pairs per CTA
#define ROWS      128           // MMA rows: h1 rows 0..63, h2 rows 64..127
#define NTHREADS  128           // 4 warps: (2 row-groups x 2 col-halves), 64x64 tiles
#define KCHUNK    32            // fp32 elems per k-chunk
#define NCHUNKS   8

#define HSTRIDE   40            // fp16 elems per H tile row (80B; proven conflict-free)
#define VSTRIDE   264           // fp16 elems per V row (528B; proven)

#define HBUF_B    (ROWS * HSTRIDE * 2)       // 10240 B per H buffer

// smem byte offsets
#define SM_H      0                          // 2 x 10240 B (double buffer)
#define SM_V      20480                      // 128 x 264 fp16 = 67584 B
#define SM_WS     88064                      // 128 floats
#define SM_SCORE  88576                      // 2 x 128 floats (per column-half)
#define SMEM_BYTES 89600

__device__ __half g_Vh[L_ * M_];

__device__ __forceinline__ float fast_tanh(float x) {
    float e = __expf(2.0f * x);
    return 1.0f - __fdividef(2.0f, e + 1.0f);
}

__device__ __forceinline__ uint32_t pack2h(float a, float b) {
    __half2 hv; hv.x = __float2half_rn(a); hv.y = __float2half_rn(b);
    return *reinterpret_cast<uint32_t*>(&hv);
}

__device__ __forceinline__ void mma_f16(float* c, const uint32_t* a,
                                        uint32_t b0, uint32_t b1) {
    asm("mma.sync.aligned.m16n8k16.row.col.f32.f16.f16.f32 "
        "{%0,%1,%2,%3}, {%4,%5,%6,%7}, {%8,%9}, {%0,%1,%2,%3};\n"
        : "+f"(c[0]), "+f"(c[1]), "+f"(c[2]), "+f"(c[3])
        : "r"(a[0]), "r"(a[1]), "r"(a[2]), "r"(a[3]), "r"(b0), "r"(b1));
}

__device__ __forceinline__ void ldsm4(uint32_t& r0, uint32_t& r1, uint32_t& r2, uint32_t& r3,
                                      uint32_t addr) {
    asm volatile("ldmatrix.sync.aligned.m8n8.x4.shared.b16 {%0,%1,%2,%3}, [%4];\n"
                 : "=r"(r0), "=r"(r1), "=r"(r2), "=r"(r3) : "r"(addr));
}

// ---------------- kernel 1: round V to fp16 ----------------
__global__ void vprep_kernel(const float* __restrict__ v_tp) {
    int i = blockIdx.x * blockDim.x + threadIdx.x;
    if (i < L_ * M_) g_Vh[i] = __float2half_rn(v_tp[i]);
}

// ---------------- kernel 2: main ----------------
extern __shared__ char smem[];

__global__ void __launch_bounds__(NTHREADS, 2)
topo_attn_kernel(const float* __restrict__ h1, const float* __restrict__ h2,
                 const float* __restrict__ w_tp, float* __restrict__ out)
{
    uint32_t sb;
    asm("{ .reg .u64 t; cvta.to.shared.u64 t, %1; cvt.u32.u64 %0, t; }"
        : "=r"(sb) : "l"(smem));

    const int tid  = threadIdx.x;
    const int warp = tid >> 5;
    const int lane = tid & 31;
    const int pair0 = blockIdx.x * PAIRS;

    float* ws     = reinterpret_cast<float*>(smem + SM_WS);
    float* scoreA = reinterpret_cast<float*>(smem + SM_SCORE);          // col half 0
    float* scoreB = scoreA + 128;                                       // col half 1
    __half* Vs    = reinterpret_cast<__half*>(smem + SM_V);

    // per-thread H staging: rows hr+16i (i<8), 8 lanes per row
    const int hr  = tid >> 3;          // 0..15
    const int hc4 = tid & 7;
    const float* pA = h1 + (size_t)(pair0 + hr) * M_;   // rows hr+16i, i<4  (h1 rows)
    const float* pB = h2 + (size_t)(pair0 + hr) * M_;   // rows hr+16i, i>=4 (h2 rows)

    // ---- issue chunk-0 LDGs immediately
    float4 f[8];
    #pragma unroll
    for (int i = 0; i < 8; ++i) {
        const float* s = (i < 4) ? (pA + (size_t)i * 16 * M_)
                                 : (pB + (size_t)(i - 4) * 16 * M_);
        f[i] = *reinterpret_cast<const float4*>(s + hc4 * 4);
    }

    // ---- while they fly: copy V (fp16, L2-resident) and w into smem
    if (tid < L_) ws[tid] = w_tp[tid];
    #pragma unroll
    for (int i = 0; i < 32; ++i) {
        int idx = i * NTHREADS + tid;      // uint4 idx over 128*32
        int r   = idx >> 5;
        int c8  = idx & 31;
        uint4 v = *reinterpret_cast<const uint4*>(g_Vh + r * M_ + c8 * 8);
        *reinterpret_cast<uint4*>(Vs + r * VSTRIDE + c8 * 8) = v;
    }

    // warp tiling: 2 row-groups x 2 col-halves, 64x64 each
    const int wr = warp >> 1;
    const int wc = warp & 1;
    const int rb = wr * 64;
    const int cb = wc * 64;

    // ldmatrix lane-address decomposition (within a 16-row / 16-col tile)
    const int arow = (lane & 7) + ((lane >> 3) & 1) * 8;
    const int acol = (lane >> 4) * 8;
    const int brow = (lane & 7) + ((lane >> 4) & 1) * 8;
    const int bcol = ((lane >> 3) & 1) * 8;

    const uint32_t a_h0 = sb + SM_H + ((rb + arow) * HSTRIDE + acol) * 2;
    const uint32_t b_v0 = sb + SM_V + ((cb + brow) * VSTRIDE + bcol) * 2;

    float acc[4][8][4];                // [row-tile m16][col-tile n8][frag]
    #pragma unroll
    for (int rt = 0; rt < 4; ++rt)
        #pragma unroll
        for (int n = 0; n < 8; ++n)
            #pragma unroll
            for (int q = 0; q < 4; ++q) acc[rt][n][q] = 0.0f;

    for (int kc = 0; kc < NCHUNKS; ++kc) {
        const int buf = kc & 1;

        // ---- cvt + store chunk kc into buf (other buffer may still be read by laggards)
        __half* Hs = reinterpret_cast<__half*>(smem + SM_H + buf * HBUF_B);
        #pragma unroll
        for (int i = 0; i < 8; ++i) {
            uint2 hv;
            hv.x = pack2h(f[i].x, f[i].y);
            hv.y = pack2h(f[i].z, f[i].w);
            *reinterpret_cast<uint2*>(Hs + (hr + i * 16) * HSTRIDE + hc4 * 4) = hv;
        }
        __syncthreads();   // buf[kc] ready; also proves all warps past mma(kc-2)

        // ---- issue next chunk's LDGs (fly under the mma below)
        if (kc + 1 < NCHUNKS) {
            #pragma unroll
            for (int i = 0; i < 8; ++i) {
                const float* s = (i < 4) ? (pA + (size_t)i * 16 * M_)
                                         : (pB + (size_t)(i - 4) * 16 * M_);
                f[i] = *reinterpret_cast<const float4*>(s + (kc + 1) * KCHUNK + hc4 * 4);
            }
        }

        // ---- mma over this chunk: 2 ksteps of k16
        const uint32_t a_hb = a_h0 + buf * HBUF_B;
        #pragma unroll
        for (int ks = 0; ks < 2; ++ks) {
            const int kk = ks * 16;
            const uint32_t kb = (kc * KCHUNK + kk) * 2;
            uint32_t bfr[4][4];
            #pragma unroll
            for (int p = 0; p < 4; ++p)
                ldsm4(bfr[p][0], bfr[p][1], bfr[p][2], bfr[p][3],
                      b_v0 + p * (16 * VSTRIDE * 2) + kb);
            #pragma unroll
            for (int rt = 0; rt < 4; ++rt) {
                uint32_t a[4];
                ldsm4(a[0], a[1], a[2], a[3], a_hb + kk * 2 + rt * (16 * HSTRIDE * 2));
                #pragma unroll
                for (int p = 0; p < 4; ++p) {
                    mma_f16(acc[rt][2 * p],     a, bfr[p][0], bfr[p][1]);
                    mma_f16(acc[rt][2 * p + 1], a, bfr[p][2], bfr[p][3]);
                }
            }
        }
    }

    // ---- epilogue: partial score over this warp's 64 columns
    {
        const int g = lane >> 2;
        const int t = lane & 3;
        float p0[4], p1[4];             // [row-tile] rows g / g+8
        #pragma unroll
        for (int rt = 0; rt < 4; ++rt) { p0[rt] = 0.f; p1[rt] = 0.f; }
        #pragma unroll
        for (int nt = 0; nt < 8; ++nt) {
            float w0 = ws[cb + nt * 8 + 2 * t];
            float w1 = ws[cb + nt * 8 + 2 * t + 1];
            #pragma unroll
            for (int rt = 0; rt < 4; ++rt) {
                p0[rt] += w0 * fast_tanh(acc[rt][nt][0]) + w1 * fast_tanh(acc[rt][nt][1]);
                p1[rt] += w0 * fast_tanh(acc[rt][nt][2]) + w1 * fast_tanh(acc[rt][nt][3]);
            }
        }
        #pragma unroll
        for (int off = 1; off < 4; off <<= 1) {
            #pragma unroll
            for (int rt = 0; rt < 4; ++rt) {
                p0[rt] += __shfl_xor_sync(0xffffffffu, p0[rt], off);
                p1[rt] += __shfl_xor_sync(0xffffffffu, p1[rt], off);
            }
        }
        if (t == 0) {
            float* sc = wc ? scoreB : scoreA;
            #pragma unroll
            for (int rt = 0; rt < 4; ++rt) {
                sc[rb + rt * 16 + g]     = p0[rt];
                sc[rb + rt * 16 + g + 8] = p1[rt];
            }
        }
    }
    __syncthreads();

    // ---- 2-way softmax + store. out shape (B, 2, T)
    if (tid < PAIRS) {
        float s1 = scoreA[tid]         + scoreB[tid];
        float s2 = scoreA[PAIRS + tid] + scoreB[PAIRS + tid];
        float d  = s2 - s1;
        float a1 = 1.0f / (1.0f + __expf(d));
        float a2 = 1.0f / (1.0f + __expf(-d));
        int gp = pair0 + tid;
        int b  = gp >> 12;          // / T_
        int tt = gp & (T_ - 1);
        out[(size_t)b * (2 * T_) + tt]      = a1;
        out[(size_t)b * (2 * T_) + T_ + tt] = a2;
    }
}

extern "C" void kernel_launch(void* const* d_in, const int* in_sizes, int n_in,
                              void* d_out, int out_size) {
    const float* h1   = (const float*)d_in[0];
    const float* h2   = (const float*)d_in[1];
    const float* w_tp = (const float*)d_in[2];
    const float* v_tp = (const float*)d_in[3];
    float* out = (float*)d_out;

    cudaFuncSetAttribute(topo_attn_kernel,
                         cudaFuncAttributeMaxDynamicSharedMemorySize, SMEM_BYTES);

    vprep_kernel<<<(L_ * M_ + 255) / 256, 256>>>(v_tp);

    int grid = (B_ * T_) / PAIRS;   // 2048
    topo_attn_kernel<<<grid, NTHREADS, SMEM_BYTES>>>(h1, h2, w_tp, out);
}

// round 15
// speedup vs baseline: 1.5939x; 1.1501x over previous
#include <cuda_runtime.h>
#include <cuda_fp16.h>
#include <cstdint>

// Problem constants
#define B_  32
#define T_  4096
#define M_  256     // K dim of GEMM
#define L_  128     // hidden (N dim of GEMM)

#define PAIRS     64            // (b,t) pairs per tile
#define ROWS      128           // MMA rows: h1 rows 0..63, h2 rows 64..127
#define NTHREADS  256           // 8 warps: (4 row-groups x 2 col-halves)
#define KCHUNK    32            // fp32 elems per k-chunk
#define NCHUNKS   8
#define NTILES    ((B_ * T_) / PAIRS)   // 2048

#define HSTRIDE   40            // fp16 elems per H tile row (80B; proven conflict-free)
#define VSTRIDE   264           // fp16 elems per V row (528B; proven)

#define HBUF_B    (ROWS * HSTRIDE * 2)       // 10240 B per H buffer

// smem byte offsets
#define SM_H      0                          // 2 x 10240 B (double buffer)
#define SM_V      20480                      // 128 x 264 fp16 = 67584 B
#define SM_WS     88064                      // 128 floats
#define SM_SCORE  88576                      // 2 x 128 floats (per column-half)
#define SMEM_BYTES 89600

__device__ __forceinline__ float fast_tanh(float x) {
    float e = __expf(2.0f * x);
    return 1.0f - __fdividef(2.0f, e + 1.0f);
}

__device__ __forceinline__ uint32_t pack2h(float a, float b) {
    __half2 hv; hv.x = __float2half_rn(a); hv.y = __float2half_rn(b);
    return *reinterpret_cast<uint32_t*>(&hv);
}

__device__ __forceinline__ void mma_f16(float* c, const uint32_t* a,
                                        uint32_t b0, uint32_t b1) {
    asm("mma.sync.aligned.m16n8k16.row.col.f32.f16.f16.f32 "
        "{%0,%1,%2,%3}, {%4,%5,%6,%7}, {%8,%9}, {%0,%1,%2,%3};\n"
        : "+f"(c[0]), "+f"(c[1]), "+f"(c[2]), "+f"(c[3])
        : "r"(a[0]), "r"(a[1]), "r"(a[2]), "r"(a[3]), "r"(b0), "r"(b1));
}

__device__ __forceinline__ void ldsm4(uint32_t& r0, uint32_t& r1, uint32_t& r2, uint32_t& r3,
                                      uint32_t addr) {
    asm volatile("ldmatrix.sync.aligned.m8n8.x4.shared.b16 {%0,%1,%2,%3}, [%4];\n"
                 : "=r"(r0), "=r"(r1), "=r"(r2), "=r"(r3) : "r"(addr));
}

extern __shared__ char smem[];

__global__ void __launch_bounds__(NTHREADS, 2)
topo_attn_kernel(const float* __restrict__ h1, const float* __restrict__ h2,
                 const float* __restrict__ w_tp, const float* __restrict__ v_tp,
                 float* __restrict__ out, int grid_stride)
{
    uint32_t sb;
    asm("{ .reg .u64 t; cvta.to.shared.u64 t, %1; cvt.u32.u64 %0, t; }"
        : "=r"(sb) : "l"(smem));

    const int tid  = threadIdx.x;
    const int warp = tid >> 5;
    const int lane = tid & 31;

    float* ws     = reinterpret_cast<float*>(smem + SM_WS);
    float* scoreA = reinterpret_cast<float*>(smem + SM_SCORE);          // col half 0
    float* scoreB = scoreA + 128;                                       // col half 1
    __half* Vs    = reinterpret_cast<__half*>(smem + SM_V);

    // per-thread H staging coords: 4 float4 per chunk over (128 rows x 8 c4)
    const int hr  = tid >> 3;          // 0..31 (+32*i)
    const int hc4 = tid & 7;

    // ---- first tile's hsrc + chunk-0 LDGs issued immediately
    int tile = blockIdx.x;
    const float* hsrc[4];
    #pragma unroll
    for (int i = 0; i < 4; ++i) {
        int rr = hr + i * 32;
        hsrc[i] = (rr < PAIRS)
            ? (h1 + (size_t)(tile * PAIRS + rr) * M_)
            : (h2 + (size_t)(tile * PAIRS + rr - PAIRS) * M_);
    }
    float4 f[4];
    #pragma unroll
    for (int i = 0; i < 4; ++i)
        f[i] = *reinterpret_cast<const float4*>(hsrc[i] + hc4 * 4);

    // ---- ONE-TIME: w + V (fp32 -> fp16, padded layout) while chunk-0 flies
    if (tid < L_) ws[tid] = w_tp[tid];
    #pragma unroll
    for (int i = 0; i < 32; ++i) {
        int idx = i * NTHREADS + tid;      // float4 idx over 128 rows x 64
        int r   = idx >> 6;
        int c4  = idx & 63;
        float4 v = *reinterpret_cast<const float4*>(v_tp + (size_t)r * M_ + c4 * 4);
        uint2 hv;
        hv.x = pack2h(v.x, v.y);
        hv.y = pack2h(v.z, v.w);
        *reinterpret_cast<uint2*>(Vs + r * VSTRIDE + c4 * 4) = hv;
    }

    // warp tiling: 4 row-groups x 2 col-halves (R8-proven)
    const int wr = warp >> 1;
    const int wc = warp & 1;
    const int rb = wr * 32;
    const int cb = wc * 64;

    // ldmatrix lane-address decomposition
    const int arow = (lane & 7) + ((lane >> 3) & 1) * 8;
    const int acol = (lane >> 4) * 8;
    const int brow = (lane & 7) + ((lane >> 4) & 1) * 8;
    const int bcol = ((lane >> 3) & 1) * 8;

    const uint32_t a_h0 = sb + SM_H + ((rb + arow) * HSTRIDE + acol) * 2;
    const uint32_t b_v0 = sb + SM_V + ((cb + brow) * VSTRIDE + bcol) * 2;

    __syncthreads();   // V + ws visible (covers first tile; later tiles reuse)

    // =================== persistent tile loop ===================
    for (; tile < NTILES; tile += grid_stride) {
        const int pair0 = tile * PAIRS;
        const int next_tile = tile + grid_stride;

        float acc[2][8][4];
        #pragma unroll
        for (int rt = 0; rt < 2; ++rt)
            #pragma unroll
            for (int n = 0; n < 8; ++n)
                #pragma unroll
                for (int q = 0; q < 4; ++q) acc[rt][n][q] = 0.0f;

        for (int kc = 0; kc < NCHUNKS; ++kc) {
            const int buf = kc & 1;

            // ---- cvt + store chunk kc into buf
            __half* Hs = reinterpret_cast<__half*>(smem + SM_H + buf * HBUF_B);
            #pragma unroll
            for (int i = 0; i < 4; ++i) {
                uint2 hv;
                hv.x = pack2h(f[i].x, f[i].y);
                hv.y = pack2h(f[i].z, f[i].w);
                *reinterpret_cast<uint2*>(Hs + (hr + i * 32) * HSTRIDE + hc4 * 4) = hv;
            }
            __syncthreads();   // buf[kc] ready; all warps past mma(kc-2)

            // ---- issue next chunk's LDGs (fly under the mma below);
            //      at kc==7 issue NEXT TILE's chunk 0 instead (hidden under mma+epilogue)
            if (kc + 1 < NCHUNKS) {
                #pragma unroll
                for (int i = 0; i < 4; ++i)
                    f[i] = *reinterpret_cast<const float4*>(hsrc[i] + (kc + 1) * KCHUNK + hc4 * 4);
            } else if (next_tile < NTILES) {
                #pragma unroll
                for (int i = 0; i < 4; ++i) {
                    int rr = hr + i * 32;
                    hsrc[i] = (rr < PAIRS)
                        ? (h1 + (size_t)(next_tile * PAIRS + rr) * M_)
                        : (h2 + (size_t)(next_tile * PAIRS + rr - PAIRS) * M_);
                    f[i] = *reinterpret_cast<const float4*>(hsrc[i] + hc4 * 4);
                }
            }

            // ---- mma over this chunk: 2 ksteps of k16
            const uint32_t a_hb = a_h0 + buf * HBUF_B;
            #pragma unroll
            for (int ks = 0; ks < 2; ++ks) {
                const int kk = ks * 16;
                uint32_t a0[4], a1[4];
                ldsm4(a0[0], a0[1], a0[2], a0[3], a_hb + kk * 2);
                ldsm4(a1[0], a1[1], a1[2], a1[3], a_hb + kk * 2 + 16 * HSTRIDE * 2);
                const uint32_t kb = (kc * KCHUNK + kk) * 2;
                #pragma unroll
                for (int p = 0; p < 4; ++p) {
                    uint32_t b0, b1, b2, b3;
                    ldsm4(b0, b1, b2, b3, b_v0 + p * (16 * VSTRIDE * 2) + kb);
                    mma_f16(acc[0][2 * p],     a0, b0, b1);
                    mma_f16(acc[0][2 * p + 1], a0, b2, b3);
                    mma_f16(acc[1][2 * p],     a1, b0, b1);
                    mma_f16(acc[1][2 * p + 1], a1, b2, b3);
                }
            }
        }

        // ---- epilogue: partial score over this warp's 64 columns
        {
            const int g = lane >> 2;
            const int t = lane & 3;
            float p0[2], p1[2];
            #pragma unroll
            for (int rt = 0; rt < 2; ++rt) { p0[rt] = 0.f; p1[rt] = 0.f; }
            #pragma unroll
            for (int nt = 0; nt < 8; ++nt) {
                float w0 = ws[cb + nt * 8 + 2 * t];
                float w1 = ws[cb + nt * 8 + 2 * t + 1];
                #pragma unroll
                for (int rt = 0; rt < 2; ++rt) {
                    p0[rt] += w0 * fast_tanh(acc[rt][nt][0]) + w1 * fast_tanh(acc[rt][nt][1]);
                    p1[rt] += w0 * fast_tanh(acc[rt][nt][2]) + w1 * fast_tanh(acc[rt][nt][3]);
                }
            }
            #pragma unroll
            for (int off = 1; off < 4; off <<= 1) {
                #pragma unroll
                for (int rt = 0; rt < 2; ++rt) {
                    p0[rt] += __shfl_xor_sync(0xffffffffu, p0[rt], off);
                    p1[rt] += __shfl_xor_sync(0xffffffffu, p1[rt], off);
                }
            }
            if (t == 0) {
                float* sc = wc ? scoreB : scoreA;
                #pragma unroll
                for (int rt = 0; rt < 2; ++rt) {
                    sc[rb + rt * 16 + g]     = p0[rt];
                    sc[rb + rt * 16 + g + 8] = p1[rt];
                }
            }
        }
        __syncthreads();

        // ---- 2-way softmax + store. out shape (B, 2, T)
        if (tid < PAIRS) {
            float s1 = scoreA[tid]         + scoreB[tid];
            float s2 = scoreA[PAIRS + tid] + scoreB[PAIRS + tid];
            float d  = s2 - s1;
            float a1 = 1.0f / (1.0f + __expf(d));
            float a2 = 1.0f / (1.0f + __expf(-d));
            int gp = pair0 + tid;
            int b  = gp >> 12;          // / T_
            int tt = gp & (T_ - 1);
            out[(size_t)b * (2 * T_) + tt]      = a1;
            out[(size_t)b * (2 * T_) + T_ + tt] = a2;
        }
        // no extra sync needed: next tile's first cvt targets H buffers (not score),
        // and next score writes are behind 8 __syncthreads
    }
}

extern "C" void kernel_launch(void* const* d_in, const int* in_sizes, int n_in,
                              void* d_out, int out_size) {
    const float* h1   = (const float*)d_in[0];
    const float* h2   = (const float*)d_in[1];
    const float* w_tp = (const float*)d_in[2];
    const float* v_tp = (const float*)d_in[3];
    float* out = (float*)d_out;

    cudaFuncSetAttribute(topo_attn_kernel,
                         cudaFuncAttributeMaxDynamicSharedMemorySize, SMEM_BYTES);

    int sms = 148;
    cudaDeviceGetAttribute(&sms, cudaDevAttrMultiProcessorCount, 0);
    int grid = 2 * sms;                 // persistent: 2 CTAs per SM
    if (grid > NTILES) grid = NTILES;

    topo_attn_kernel<<<grid, NTHREADS, SMEM_BYTES>>>(h1, h2, w_tp, v_tp, out, grid);
}

// round 16
// speedup vs baseline: 1.7863x; 1.1207x over previous
#include <cuda_runtime.h>
#include <cuda_fp16.h>
#include <cstdint>

// Problem constants
#define B_  32
#define T_  4096
#define M_  256     // K dim of GEMM
#define L_  128     // hidden (N dim of GEMM)

#define PAIRS     64            // (b,t) pairs per tile
#define ROWS      128           // MMA rows: h1 rows 0..63, h2 rows 64..127
#define NTHREADS  256           // 8 warps: (4 row-groups x 2 col-halves)
#define KCHUNK    32            // fp32 elems per k-chunk
#define NCHUNKS   8
#define NTILES    ((B_ * T_) / PAIRS)   // 2048

#define HSTRIDE   40            // fp16 elems per H tile row (80B; proven conflict-free)
#define VSTRIDE   264           // fp16 elems per V row (528B; proven)

#define HBUF_B    (ROWS * HSTRIDE * 2)       // 10240 B per H buffer

// smem byte offsets
#define SM_H      0                          // 2 x 10240 B (double buffer)
#define SM_V      20480                      // 128 x 264 fp16 = 67584 B
#define SM_WS     88064                      // 128 floats
#define SM_SCORE  88576                      // 2 x 128 floats (per column-half)
#define SMEM_BYTES 89600

__device__ __forceinline__ float fast_tanh(float x) {
    float r;
    asm("tanh.approx.f32 %0, %1;" : "=f"(r) : "f"(x));
    return r;
}

__device__ __forceinline__ uint32_t pack2h(float a, float b) {
    __half2 hv; hv.x = __float2half_rn(a); hv.y = __float2half_rn(b);
    return *reinterpret_cast<uint32_t*>(&hv);
}

__device__ __forceinline__ void mma_f16(float* c, const uint32_t* a,
                                        uint32_t b0, uint32_t b1) {
    asm("mma.sync.aligned.m16n8k16.row.col.f32.f16.f16.f32 "
        "{%0,%1,%2,%3}, {%4,%5,%6,%7}, {%8,%9}, {%0,%1,%2,%3};\n"
        : "+f"(c[0]), "+f"(c[1]), "+f"(c[2]), "+f"(c[3])
        : "r"(a[0]), "r"(a[1]), "r"(a[2]), "r"(a[3]), "r"(b0), "r"(b1));
}

__device__ __forceinline__ void ldsm4(uint32_t& r0, uint32_t& r1, uint32_t& r2, uint32_t& r3,
                                      uint32_t addr) {
    asm volatile("ldmatrix.sync.aligned.m8n8.x4.shared.b16 {%0,%1,%2,%3}, [%4];\n"
                 : "=r"(r0), "=r"(r1), "=r"(r2), "=r"(r3) : "r"(addr));
}

extern __shared__ char smem[];

__global__ void __launch_bounds__(NTHREADS, 2)
topo_attn_kernel(const float* __restrict__ h1, const float* __restrict__ h2,
                 const float* __restrict__ w_tp, const float* __restrict__ v_tp,
                 float* __restrict__ out, int grid_stride)
{
    uint32_t sb;
    asm("{ .reg .u64 t; cvta.to.shared.u64 t, %1; cvt.u32.u64 %0, t; }"
        : "=r"(sb) : "l"(smem));

    const int tid  = threadIdx.x;
    const int warp = tid >> 5;
    const int lane = tid & 31;

    float* ws     = reinterpret_cast<float*>(smem + SM_WS);
    float* scoreA = reinterpret_cast<float*>(smem + SM_SCORE);          // col half 0
    float* scoreB = scoreA + 128;                                       // col half 1
    __half* Vs    = reinterpret_cast<__half*>(smem + SM_V);

    // per-thread H staging coords: 4 float4 per chunk over (128 rows x 8 c4)
    const int hr  = tid >> 3;          // 0..31 (+32*i)
    const int hc4 = tid & 7;

    // ---- first tile's hsrc + chunk-0 LDGs issued immediately
    int tile = blockIdx.x;
    const float* hsrc[4];
    #pragma unroll
    for (int i = 0; i < 4; ++i) {
        int rr = hr + i * 32;
        hsrc[i] = (rr < PAIRS)
            ? (h1 + (size_t)(tile * PAIRS + rr) * M_)
            : (h2 + (size_t)(tile * PAIRS + rr - PAIRS) * M_);
    }
    float4 f[4];
    #pragma unroll
    for (int i = 0; i < 4; ++i)
        f[i] = *reinterpret_cast<const float4*>(hsrc[i] + hc4 * 4);

    // ---- ONE-TIME: w + V (fp32 -> fp16, padded layout) while chunk-0 flies
    if (tid < L_) ws[tid] = w_tp[tid];
    #pragma unroll
    for (int i = 0; i < 32; ++i) {
        int idx = i * NTHREADS + tid;      // float4 idx over 128 rows x 64
        int r   = idx >> 6;
        int c4  = idx & 63;
        float4 v = *reinterpret_cast<const float4*>(v_tp + (size_t)r * M_ + c4 * 4);
        uint2 hv;
        hv.x = pack2h(v.x, v.y);
        hv.y = pack2h(v.z, v.w);
        *reinterpret_cast<uint2*>(Vs + r * VSTRIDE + c4 * 4) = hv;
    }

    // warp tiling: 4 row-groups x 2 col-halves (R8-proven)
    const int wr = warp >> 1;
    const int wc = warp & 1;
    const int rb = wr * 32;
    const int cb = wc * 64;

    // ldmatrix lane-address decomposition
    const int arow = (lane & 7) + ((lane >> 3) & 1) * 8;
    const int acol = (lane >> 4) * 8;
    const int brow = (lane & 7) + ((lane >> 4) & 1) * 8;
    const int bcol = ((lane >> 3) & 1) * 8;

    const uint32_t a_h0 = sb + SM_H + ((rb + arow) * HSTRIDE + acol) * 2;
    const uint32_t b_v0 = sb + SM_V + ((cb + brow) * VSTRIDE + bcol) * 2;

    __syncthreads();   // V + ws visible (covers first tile; later tiles reuse)

    // =================== persistent tile loop ===================
    for (; tile < NTILES; tile += grid_stride) {
        const int pair0 = tile * PAIRS;
        const int next_tile = tile + grid_stride;

        float acc[2][8][4];
        #pragma unroll
        for (int rt = 0; rt < 2; ++rt)
            #pragma unroll
            for (int n = 0; n < 8; ++n)
                #pragma unroll
                for (int q = 0; q < 4; ++q) acc[rt][n][q] = 0.0f;

        for (int kc = 0; kc < NCHUNKS; ++kc) {
            const int buf = kc & 1;

            // ---- cvt + store chunk kc into buf
            __half* Hs = reinterpret_cast<__half*>(smem + SM_H + buf * HBUF_B);
            #pragma unroll
            for (int i = 0; i < 4; ++i) {
                uint2 hv;
                hv.x = pack2h(f[i].x, f[i].y);
                hv.y = pack2h(f[i].z, f[i].w);
                *reinterpret_cast<uint2*>(Hs + (hr + i * 32) * HSTRIDE + hc4 * 4) = hv;
            }

            // ---- issue next chunk's LDGs BEFORE the barrier (latency overlaps
            //      the barrier drain); f already consumed by the cvt above.
            //      At kc==7 issue NEXT TILE's chunk 0 instead.
            if (kc + 1 < NCHUNKS) {
                #pragma unroll
                for (int i = 0; i < 4; ++i)
                    f[i] = *reinterpret_cast<const float4*>(hsrc[i] + (kc + 1) * KCHUNK + hc4 * 4);
            } else if (next_tile < NTILES) {
                #pragma unroll
                for (int i = 0; i < 4; ++i) {
                    int rr = hr + i * 32;
                    hsrc[i] = (rr < PAIRS)
                        ? (h1 + (size_t)(next_tile * PAIRS + rr) * M_)
                        : (h2 + (size_t)(next_tile * PAIRS + rr - PAIRS) * M_);
                    f[i] = *reinterpret_cast<const float4*>(hsrc[i] + hc4 * 4);
                }
            }

            __syncthreads();   // buf[kc] ready; all warps past mma(kc-2)

            // ---- mma over this chunk: 2 ksteps of k16
            const uint32_t a_hb = a_h0 + buf * HBUF_B;
            #pragma unroll
            for (int ks = 0; ks < 2; ++ks) {
                const int kk = ks * 16;
                uint32_t a0[4], a1[4];
                ldsm4(a0[0], a0[1], a0[2], a0[3], a_hb + kk * 2);
                ldsm4(a1[0], a1[1], a1[2], a1[3], a_hb + kk * 2 + 16 * HSTRIDE * 2);
                const uint32_t kb = (kc * KCHUNK + kk) * 2;
                #pragma unroll
                for (int p = 0; p < 4; ++p) {
                    uint32_t b0, b1, b2, b3;
                    ldsm4(b0, b1, b2, b3, b_v0 + p * (16 * VSTRIDE * 2) + kb);
                    mma_f16(acc[0][2 * p],     a0, b0, b1);
                    mma_f16(acc[0][2 * p + 1], a0, b2, b3);
                    mma_f16(acc[1][2 * p],     a1, b0, b1);
                    mma_f16(acc[1][2 * p + 1], a1, b2, b3);
                }
            }
        }

        // ---- epilogue: partial score over this warp's 64 columns
        {
            const int g = lane >> 2;
            const int t = lane & 3;
            float p0[2], p1[2];
            #pragma unroll
            for (int rt = 0; rt < 2; ++rt) { p0[rt] = 0.f; p1[rt] = 0.f; }
            #pragma unroll
            for (int nt = 0; nt < 8; ++nt) {
                float w0 = ws[cb + nt * 8 + 2 * t];
                float w1 = ws[cb + nt * 8 + 2 * t + 1];
                #pragma unroll
                for (int rt = 0; rt < 2; ++rt) {
                    p0[rt] += w0 * fast_tanh(acc[rt][nt][0]) + w1 * fast_tanh(acc[rt][nt][1]);
                    p1[rt] += w0 * fast_tanh(acc[rt][nt][2]) + w1 * fast_tanh(acc[rt][nt][3]);
                }
            }
            #pragma unroll
            for (int off = 1; off < 4; off <<= 1) {
                #pragma unroll
                for (int rt = 0; rt < 2; ++rt) {
                    p0[rt] += __shfl_xor_sync(0xffffffffu, p0[rt], off);
                    p1[rt] += __shfl_xor_sync(0xffffffffu, p1[rt], off);
                }
            }
            if (t == 0) {
                float* sc = wc ? scoreB : scoreA;
                #pragma unroll
                for (int rt = 0; rt < 2; ++rt) {
                    sc[rb + rt * 16 + g]     = p0[rt];
                    sc[rb + rt * 16 + g + 8] = p1[rt];
                }
            }
        }
        __syncthreads();

        // ---- 2-way softmax + store. out shape (B, 2, T)
        //      a1 = 1/(1+e^d) = 0.5*(1 - tanh(d/2)); a2 = 1 - a1
        if (tid < PAIRS) {
            float s1 = scoreA[tid]         + scoreB[tid];
            float s2 = scoreA[PAIRS + tid] + scoreB[PAIRS + tid];
            float th = fast_tanh(0.5f * (s2 - s1));
            float a1 = 0.5f - 0.5f * th;
            float a2 = 0.5f + 0.5f * th;
            int gp = pair0 + tid;
            int b  = gp >> 12;          // / T_
            int tt = gp & (T_ - 1);
            out[(size_t)b * (2 * T_) + tt]      = a1;
            out[(size_t)b * (2 * T_) + T_ + tt] = a2;
        }
        // no extra sync needed: next tile's first cvt targets H buffers (not score),
        // and next score writes are behind 8 __syncthreads
    }
}

extern "C" void kernel_launch(void* const* d_in, const int* in_sizes, int n_in,
                              void* d_out, int out_size) {
    const float* h1   = (const float*)d_in[0];
    const float* h2   = (const float*)d_in[1];
    const float* w_tp = (const float*)d_in[2];
    const float* v_tp = (const float*)d_in[3];
    float* out = (float*)d_out;

    cudaFuncSetAttribute(topo_attn_kernel,
                         cudaFuncAttributeMaxDynamicSharedMemorySize, SMEM_BYTES);

    int sms = 148;
    cudaDeviceGetAttribute(&sms, cudaDevAttrMultiProcessorCount, 0);
    int grid = 2 * sms;                 // persistent: 2 CTAs per SM
    if (grid > NTILES) grid = NTILES;

    topo_attn_kernel<<<grid, NTHREADS, SMEM_BYTES>>>(h1, h2, w_tp, v_tp, out, grid);
}